// round 2
// baseline (speedup 1.0000x reference)
#include <cuda_runtime.h>
#include <math.h>

// ---------------------------------------------------------------------------
// Problem constants
// ---------------------------------------------------------------------------
namespace {
constexpr int B_ = 4, T_ = 2048, D_ = 2048, H_ = 32, HS_ = 64;
constexpr int BT_ = B_ * T_;            // 8192
constexpr int E5_ = 160, TD_ = 64;
constexpr long long BTD_ = (long long)BT_ * D_;   // 16,777,216

constexpr size_t SEG = (size_t)BT_ * D_;
constexpr size_t S_SX   = 0;
constexpr size_t S_XXX  = 1 * SEG;
constexpr size_t S_WX   = 2 * SEG;
constexpr size_t S_KX   = 3 * SEG;
constexpr size_t S_VX   = 4 * SEG;
constexpr size_t S_RX   = 5 * SEG;
constexpr size_t S_GX   = 6 * SEG;
constexpr size_t S_R    = 7 * SEG;
constexpr size_t S_K    = 8 * SEG;
constexpr size_t S_V    = 9 * SEG;
constexpr size_t S_GATE = 10 * SEG;
constexpr size_t S_W    = 11 * SEG;
constexpr size_t S_WKV  = 12 * SEG;
constexpr size_t S_GG   = 13 * SEG;
constexpr size_t S_M    = 14 * SEG;
constexpr size_t S_WTMP = S_M + (size_t)BT_ * E5_;
constexpr size_t SCRATCH_FLOATS = S_WTMP + (size_t)BT_ * TD_;
}

__device__ __align__(256) float g_scratch[SCRATCH_FLOATS];

// ---------------------------------------------------------------------------
// prep: sx = shift(x) - x ; xxx = x + sx * x_maa ; x_last output
// ---------------------------------------------------------------------------
__global__ __launch_bounds__(256) void prep_kernel(
    const float* __restrict__ x, const float* __restrict__ prev,
    const float* __restrict__ x_maa, float* __restrict__ xlast)
{
    size_t i4 = (size_t)blockIdx.x * 256 + threadIdx.x;   // float4 index
    if (i4 >= (size_t)(BTD_ / 4)) return;
    size_t idx = i4 * 4;
    int d = (int)(idx % D_);
    size_t bt = idx / D_;
    int t = (int)(bt % T_);
    int b = (int)(bt / T_);

    float4 xv = *(const float4*)(x + idx);
    float4 sh = (t > 0) ? *(const float4*)(x + idx - D_)
                        : *(const float4*)(prev + (size_t)b * D_ + d);
    float4 ma = *(const float4*)(x_maa + d);
    float4 sx, xx;
    sx.x = sh.x - xv.x; sx.y = sh.y - xv.y; sx.z = sh.z - xv.z; sx.w = sh.w - xv.w;
    xx.x = fmaf(sx.x, ma.x, xv.x); xx.y = fmaf(sx.y, ma.y, xv.y);
    xx.z = fmaf(sx.z, ma.z, xv.z); xx.w = fmaf(sx.w, ma.w, xv.w);
    *(float4*)(g_scratch + S_SX + idx)  = sx;
    *(float4*)(g_scratch + S_XXX + idx) = xx;
    if (t == T_ - 1)
        *(float4*)(xlast + (size_t)b * D_ + d) = xv;
}

// ---------------------------------------------------------------------------
// Tiled fp32 GEMM, C[M,N] = A[M,K] @ B[K,N], row-major, fused epilogues.
// BM=BN=128, BK=16, 256 threads, 8x8 per-thread microtile, reg prefetch.
// M must be a multiple of 128, K a multiple of 16. N guarded (N%4==0).
// ---------------------------------------------------------------------------
enum { EPI_NONE = 0, EPI_TANH, EPI_SIG, EPI_SILU, EPI_BLEND, EPI_WDECAY };

template<int EPI>
__device__ __forceinline__ float epi_apply(float v, size_t idx, int col,
    const float* e1, const float* e2, const float* e3)
{
    if (EPI == EPI_TANH)   return tanhf(v);
    if (EPI == EPI_SIG)    return 1.f / (1.f + expf(-v));
    if (EPI == EPI_SILU)   return v / (1.f + expf(-v));
    if (EPI == EPI_BLEND)  return fmaf(e2[idx], e3[col] + v, e1[idx]); // x + sx*(maa+m)
    if (EPI == EPI_WDECAY) return expf(-expf(v + e3[col]));
    return v;
}

template<int EPI>
__global__ __launch_bounds__(256)
void sgemm_k(const float* __restrict__ A, int lda,
             const float* __restrict__ Bg, int ldb,
             float* __restrict__ C, int ldc,
             int N, int K,
             const float* __restrict__ e1, const float* __restrict__ e2,
             const float* __restrict__ e3)
{
    __shared__ __align__(16) float As[16][132];   // [k][m], pad=4 keeps 16B align
    __shared__ __align__(16) float Bs[16][128];   // [k][n]

    const int tid = threadIdx.x;
    const int rowBase = blockIdx.y * 128;
    const int colBase = blockIdx.x * 128;

    const int a_row = tid >> 2;          // 0..63 (and +64)
    const int a_k   = (tid & 3) * 4;     // 0,4,8,12
    const int b_k   = tid >> 5;          // 0..7 (and +8)
    const int b_c   = (tid & 31) * 4;    // 0..124
    const int tx = tid & 15, ty = tid >> 4;

    float acc[8][8];
    #pragma unroll
    for (int i = 0; i < 8; i++)
        #pragma unroll
        for (int j = 0; j < 8; j++) acc[i][j] = 0.f;

    const int ktiles = K >> 4;
    const bool bok = (colBase + b_c) < N;
    const float4 zf4 = make_float4(0.f, 0.f, 0.f, 0.f);

    const float* Ag0 = A + (size_t)(rowBase + a_row) * lda + a_k;
    const float* Ag1 = Ag0 + (size_t)64 * lda;
    const float* Bg0 = Bg + (size_t)b_k * ldb + colBase + b_c;
    const float* Bg1 = Bg0 + (size_t)8 * ldb;

    float4 pa0 = *(const float4*)Ag0;
    float4 pa1 = *(const float4*)Ag1;
    float4 pb0 = bok ? *(const float4*)Bg0 : zf4;
    float4 pb1 = bok ? *(const float4*)Bg1 : zf4;

    for (int kt = 0; kt < ktiles; ++kt) {
        As[a_k + 0][a_row]      = pa0.x; As[a_k + 1][a_row]      = pa0.y;
        As[a_k + 2][a_row]      = pa0.z; As[a_k + 3][a_row]      = pa0.w;
        As[a_k + 0][a_row + 64] = pa1.x; As[a_k + 1][a_row + 64] = pa1.y;
        As[a_k + 2][a_row + 64] = pa1.z; As[a_k + 3][a_row + 64] = pa1.w;
        *(float4*)&Bs[b_k][b_c]     = pb0;
        *(float4*)&Bs[b_k + 8][b_c] = pb1;
        __syncthreads();

        if (kt + 1 < ktiles) {
            pa0 = *(const float4*)(Ag0 + (size_t)(kt + 1) * 16);
            pa1 = *(const float4*)(Ag1 + (size_t)(kt + 1) * 16);
            pb0 = bok ? *(const float4*)(Bg0 + (size_t)(kt + 1) * 16 * ldb) : zf4;
            pb1 = bok ? *(const float4*)(Bg1 + (size_t)(kt + 1) * 16 * ldb) : zf4;
        }

        #pragma unroll
        for (int kk = 0; kk < 16; ++kk) {
            float4 a0 = *(const float4*)&As[kk][ty * 4];
            float4 a1 = *(const float4*)&As[kk][ty * 4 + 64];
            float4 b0 = *(const float4*)&Bs[kk][tx * 4];
            float4 b1 = *(const float4*)&Bs[kk][tx * 4 + 64];
            float av[8] = {a0.x, a0.y, a0.z, a0.w, a1.x, a1.y, a1.z, a1.w};
            float bv[8] = {b0.x, b0.y, b0.z, b0.w, b1.x, b1.y, b1.z, b1.w};
            #pragma unroll
            for (int i = 0; i < 8; i++)
                #pragma unroll
                for (int j = 0; j < 8; j++)
                    acc[i][j] = fmaf(av[i], bv[j], acc[i][j]);
        }
        __syncthreads();
    }

    #pragma unroll
    for (int i = 0; i < 8; i++) {
        int r = rowBase + ty * 4 + (i & 3) + (i >> 2) * 64;
        #pragma unroll
        for (int jh = 0; jh < 2; jh++) {
            int c = colBase + tx * 4 + jh * 64;
            if (c < N) {
                size_t idx = (size_t)r * ldc + c;
                float4 o;
                o.x = epi_apply<EPI>(acc[i][jh * 4 + 0], idx + 0, c + 0, e1, e2, e3);
                o.y = epi_apply<EPI>(acc[i][jh * 4 + 1], idx + 1, c + 1, e1, e2, e3);
                o.z = epi_apply<EPI>(acc[i][jh * 4 + 2], idx + 2, c + 2, e1, e2, e3);
                o.w = epi_apply<EPI>(acc[i][jh * 4 + 3], idx + 3, c + 3, e1, e2, e3);
                *(float4*)(C + idx) = o;
            }
        }
    }
}

// ---------------------------------------------------------------------------
// WKV scan: one block per (b,h). 256 threads: thread = (j = tid>>2, q = tid&3),
// i = ii*4+q (interleaved so LDS of r/k/w is conflict-free broadcast).
// r/k/v/w staged into shared in chunks of 32 timesteps. In-warp shfl reduce.
// ---------------------------------------------------------------------------
constexpr int WKV_CH = 32;

__global__ __launch_bounds__(256) void wkv_kernel(
    const float* __restrict__ u, const float* __restrict__ state_in,
    float* __restrict__ state_out)
{
    const float* r = g_scratch + S_R;
    const float* k = g_scratch + S_K;
    const float* v = g_scratch + S_V;
    const float* w = g_scratch + S_W;
    float*       o = g_scratch + S_WKV;

    int bh = blockIdx.x;
    int b = bh / H_, h = bh % H_;
    int tid = threadIdx.x;
    int j = tid >> 2, q = tid & 3;

    float st[16], uu[16];
    const float* sin = state_in + (size_t)bh * HS_ * HS_;
    #pragma unroll
    for (int ii = 0; ii < 16; ii++) {
        int i = ii * 4 + q;
        st[ii] = sin[i * HS_ + j];
        uu[ii] = u[h * HS_ + i];
    }

    __shared__ __align__(16) float sr[WKV_CH][64];
    __shared__ __align__(16) float sk[WKV_CH][64];
    __shared__ __align__(16) float sv[WKV_CH][64];
    __shared__ __align__(16) float sw[WKV_CH][64];

    size_t rowBase = (size_t)(b * T_) * D_ + h * HS_;

    for (int t0 = 0; t0 < T_; t0 += WKV_CH) {
        __syncthreads();
        #pragma unroll
        for (int l = 0; l < 2; l++) {
            int f4 = tid + l * 256;          // 0..511 float4 slots
            int s  = f4 >> 4;
            int c  = (f4 & 15) * 4;
            size_t g = rowBase + (size_t)(t0 + s) * D_ + c;
            *(float4*)&sr[s][c] = *(const float4*)(r + g);
            *(float4*)&sk[s][c] = *(const float4*)(k + g);
            *(float4*)&sv[s][c] = *(const float4*)(v + g);
            *(float4*)&sw[s][c] = *(const float4*)(w + g);
        }
        __syncthreads();

        for (int s = 0; s < WKV_CH; s++) {
            float vj = sv[s][j];
            float acc = 0.f, acc2 = 0.f;
            #pragma unroll
            for (int ii = 0; ii < 16; ii++) {
                int i = ii * 4 + q;
                float ri = sr[s][i], ki = sk[s][i], wi = sw[s][i];
                acc  = fmaf(ri, st[ii], acc);            // r . state  (old state)
                acc2 = fmaf(ri * ki, uu[ii], acc2);      // r . (u*k)
                st[ii] = fmaf(st[ii], wi, ki * vj);      // state = state*w + k*v
            }
            acc  += __shfl_xor_sync(0xffffffffu, acc, 1);
            acc  += __shfl_xor_sync(0xffffffffu, acc, 2);
            acc2 += __shfl_xor_sync(0xffffffffu, acc2, 1);
            acc2 += __shfl_xor_sync(0xffffffffu, acc2, 2);
            if (q == 0)
                o[rowBase + (size_t)(t0 + s) * D_ + j] = fmaf(vj, acc2, acc);
        }
    }

    float* sout = state_out + (size_t)bh * HS_ * HS_;
    #pragma unroll
    for (int ii = 0; ii < 16; ii++)
        sout[(ii * 4 + q) * HS_ + j] = st[ii];
}

// ---------------------------------------------------------------------------
// GroupNorm over HS per (bt,h) + ln scale/bias + multiply by silu gate.
// One warp per group (64 values, 2 per lane).
// ---------------------------------------------------------------------------
__global__ __launch_bounds__(256) void gnorm_kernel(
    const float* __restrict__ lng, const float* __restrict__ lnb)
{
    const float* wkv  = g_scratch + S_WKV;
    const float* gate = g_scratch + S_GATE;
    float*       out  = g_scratch + S_GG;

    int gid  = blockIdx.x * 8 + (threadIdx.x >> 5);   // group in [0, BT*H)
    int lane = threadIdx.x & 31;
    size_t base = (size_t)gid * 64;

    float v0 = wkv[base + lane], v1 = wkv[base + 32 + lane];
    float s = v0 + v1, ss = v0 * v0 + v1 * v1;
    #pragma unroll
    for (int off = 16; off > 0; off >>= 1) {
        s  += __shfl_xor_sync(0xffffffffu, s, off);
        ss += __shfl_xor_sync(0xffffffffu, ss, off);
    }
    float mu   = s * (1.f / 64.f);
    float var  = ss * (1.f / 64.f) - mu * mu;
    float rstd = rsqrtf(var + 1e-5f);

    int h  = gid & (H_ - 1);
    int d0 = h * 64 + lane, d1 = d0 + 32;
    out[base + lane]      = fmaf((v0 - mu) * rstd, lng[d0], lnb[d0]) * gate[base + lane];
    out[base + 32 + lane] = fmaf((v1 - mu) * rstd, lng[d1], lnb[d1]) * gate[base + 32 + lane];
}

// ---------------------------------------------------------------------------
// Launch
// ---------------------------------------------------------------------------
extern "C" void kernel_launch(void* const* d_in, const int* in_sizes, int n_in,
                              void* d_out, int out_size)
{
    const float* x     = (const float*)d_in[0];
    const float* prev  = (const float*)d_in[1];
    const float* st0   = (const float*)d_in[2];
    const float* x_maa = (const float*)d_in[3];
    const float* w_maa = (const float*)d_in[4];
    const float* k_maa = (const float*)d_in[5];
    const float* v_maa = (const float*)d_in[6];
    const float* r_maa = (const float*)d_in[7];
    const float* g_maa = (const float*)d_in[8];
    const float* tm_w1 = (const float*)d_in[9];
    const float* tm_w2 = (const float*)d_in[10];
    const float* td_w1 = (const float*)d_in[11];
    const float* td_w2 = (const float*)d_in[12];
    const float* decay = (const float*)d_in[13];
    const float* first = (const float*)d_in[14];
    const float* W_r   = (const float*)d_in[15];
    const float* W_k   = (const float*)d_in[16];
    const float* W_v   = (const float*)d_in[17];
    const float* W_g   = (const float*)d_in[18];
    const float* W_o   = (const float*)d_in[19];
    const float* ln_g  = (const float*)d_in[20];
    const float* ln_b  = (const float*)d_in[21];

    float* out       = (float*)d_out;
    float* out_xlast = out + BTD_;
    float* out_state = out + BTD_ + (size_t)B_ * D_;

    float* S = nullptr;
    cudaGetSymbolAddress((void**)&S, g_scratch);

    dim3 blk(256);

    // 1) shift / sx / xxx / x_last
    prep_kernel<<<(unsigned)(BTD_ / 4 / 256), blk>>>(x, prev, x_maa, out_xlast);

    // 2) m = tanh(xxx @ tm_w1)   [8192 x 160, K=2048]
    sgemm_k<EPI_TANH><<<dim3(2, BT_ / 128), blk>>>(
        S + S_XXX, D_, tm_w1, E5_, S + S_M, E5_, E5_, D_,
        nullptr, nullptr, nullptr);

    // 3) five token-mix blends: buf_f = x + sx*(maa_f + m_f @ tm_w2[f])  [K=32]
    const float* maas[5] = {w_maa, k_maa, v_maa, r_maa, g_maa};
    const size_t tgts[5] = {S_WX, S_KX, S_VX, S_RX, S_GX};
    dim3 full(16, BT_ / 128);
    for (int f = 0; f < 5; ++f)
        sgemm_k<EPI_BLEND><<<full, blk>>>(
            S + S_M + f * 32, E5_, tm_w2 + (size_t)f * 32 * D_, D_,
            S + tgts[f], D_, D_, 32, x, S + S_SX, maas[f]);

    // 4) projections
    sgemm_k<EPI_SIG ><<<full, blk>>>(S + S_RX, D_, W_r, D_, S + S_R,    D_, D_, D_, nullptr, nullptr, nullptr);
    sgemm_k<EPI_NONE><<<full, blk>>>(S + S_KX, D_, W_k, D_, S + S_K,    D_, D_, D_, nullptr, nullptr, nullptr);
    sgemm_k<EPI_NONE><<<full, blk>>>(S + S_VX, D_, W_v, D_, S + S_V,    D_, D_, D_, nullptr, nullptr, nullptr);
    sgemm_k<EPI_SILU><<<full, blk>>>(S + S_GX, D_, W_g, D_, S + S_GATE, D_, D_, D_, nullptr, nullptr, nullptr);

    // 5) decay path: w = exp(-exp(tanh(wx@td_w1) @ td_w2 + time_decay))
    sgemm_k<EPI_TANH><<<dim3(1, BT_ / 128), blk>>>(
        S + S_WX, D_, td_w1, TD_, S + S_WTMP, TD_, TD_, D_,
        nullptr, nullptr, nullptr);
    sgemm_k<EPI_WDECAY><<<full, blk>>>(
        S + S_WTMP, TD_, td_w2, D_, S + S_W, D_, D_, TD_,
        nullptr, nullptr, decay);

    // 6) WKV scan (also writes new_state into d_out)
    wkv_kernel<<<B_ * H_, blk>>>(first, st0, out_state);

    // 7) groupnorm + ln + gate multiply
    gnorm_kernel<<<BT_ * H_ / 8, blk>>>(ln_g, ln_b);

    // 8) final projection into d_out
    sgemm_k<EPI_NONE><<<full, blk>>>(S + S_GG, D_, W_o, D_, out, D_, D_, D_,
                                     nullptr, nullptr, nullptr);
}

// round 4
// speedup vs baseline: 2.0153x; 2.0153x over previous
#include <cuda_runtime.h>
#include <cuda_bf16.h>
#include <math.h>
#include <stdint.h>

// ---------------------------------------------------------------------------
// Problem constants
// ---------------------------------------------------------------------------
namespace {
constexpr int B_ = 4, T_ = 2048, D_ = 2048, H_ = 32, HS_ = 64;
constexpr int BT_ = B_ * T_;            // 8192
constexpr int E5_ = 160, TD_ = 64;
constexpr long long BTD_ = (long long)BT_ * D_;   // 16,777,216

// fp32 scratch segments
constexpr size_t SEG = (size_t)BT_ * D_;
constexpr size_t S_SX   = 0;
constexpr size_t S_XXX  = 1 * SEG;
constexpr size_t S_WX   = 2 * SEG;
constexpr size_t S_R    = 3 * SEG;
constexpr size_t S_K    = 4 * SEG;
constexpr size_t S_V    = 5 * SEG;
constexpr size_t S_GATE = 6 * SEG;
constexpr size_t S_W    = 7 * SEG;
constexpr size_t S_WKV  = 8 * SEG;
constexpr size_t S_M    = 9 * SEG;
constexpr size_t S_WTMP = S_M + (size_t)BT_ * E5_;
constexpr size_t SCRATCH_FLOATS = S_WTMP + (size_t)BT_ * TD_;

// bf16 scratch segments: activation hi/lo pairs + transposed/split weights
constexpr size_t WSEG = (size_t)D_ * D_;
constexpr size_t B_KXH = 0,        B_KXL = 1 * SEG;
constexpr size_t B_VXH = 2 * SEG,  B_VXL = 3 * SEG;
constexpr size_t B_RXH = 4 * SEG,  B_RXL = 5 * SEG;
constexpr size_t B_GXH = 6 * SEG,  B_GXL = 7 * SEG;
constexpr size_t B_GGH = 8 * SEG,  B_GGL = 9 * SEG;
constexpr size_t B_WT0 = 10 * SEG;                    // 10 weight segs follow
constexpr size_t BF_TOTAL = B_WT0 + 10 * WSEG;
}

__device__ __align__(256) float g_scratch[SCRATCH_FLOATS];
__device__ __align__(256) __nv_bfloat16 g_bf[BF_TOTAL];

// ---------------------------------------------------------------------------
// PTX helpers (all plain compute_80-level PTX — no arch-'a' features)
// ---------------------------------------------------------------------------
__device__ __forceinline__ uint32_t smem_u32(const void* p) {
    uint32_t a;
    asm("{ .reg .u64 t; cvta.to.shared.u64 t, %1; cvt.u32.u64 %0, t; }"
        : "=r"(a) : "l"(p));
    return a;
}

__device__ __forceinline__ void cp16(uint32_t saddr, const void* g) {
    asm volatile("cp.async.cg.shared.global [%0], [%1], 16;" :: "r"(saddr), "l"(g));
}
__device__ __forceinline__ void cp_commit() { asm volatile("cp.async.commit_group;" ::: "memory"); }
__device__ __forceinline__ void cp_wait1() { asm volatile("cp.async.wait_group 1;" ::: "memory"); }
__device__ __forceinline__ void cp_wait0() { asm volatile("cp.async.wait_group 0;" ::: "memory"); }

__device__ __forceinline__ void ldmx4(uint32_t* r, uint32_t addr) {
    asm volatile("ldmatrix.sync.aligned.m8n8.x4.shared.b16 {%0,%1,%2,%3}, [%4];"
        : "=r"(r[0]), "=r"(r[1]), "=r"(r[2]), "=r"(r[3]) : "r"(addr));
}

__device__ __forceinline__ void mma16816(float* c, const uint32_t* a,
                                         uint32_t b0, uint32_t b1) {
    asm volatile(
        "mma.sync.aligned.m16n8k16.row.col.f32.bf16.bf16.f32 "
        "{%0,%1,%2,%3}, {%4,%5,%6,%7}, {%8,%9}, {%0,%1,%2,%3};"
        : "+f"(c[0]), "+f"(c[1]), "+f"(c[2]), "+f"(c[3])
        : "r"(a[0]), "r"(a[1]), "r"(a[2]), "r"(a[3]), "r"(b0), "r"(b1));
}

__device__ __forceinline__ void split2(float v, __nv_bfloat16& h, __nv_bfloat16& l) {
    h = __float2bfloat16(v);
    l = __float2bfloat16(v - __bfloat162float(h));
}

// ---------------------------------------------------------------------------
// prep: sx = shift(x) - x ; xxx = x + sx * x_maa ; x_last output
// ---------------------------------------------------------------------------
__global__ __launch_bounds__(256) void prep_kernel(
    const float* __restrict__ x, const float* __restrict__ prev,
    const float* __restrict__ x_maa, float* __restrict__ xlast)
{
    size_t i4 = (size_t)blockIdx.x * 256 + threadIdx.x;
    if (i4 >= (size_t)(BTD_ / 4)) return;
    size_t idx = i4 * 4;
    int d = (int)(idx % D_);
    size_t bt = idx / D_;
    int t = (int)(bt % T_);
    int b = (int)(bt / T_);

    float4 xv = *(const float4*)(x + idx);
    float4 sh = (t > 0) ? *(const float4*)(x + idx - D_)
                        : *(const float4*)(prev + (size_t)b * D_ + d);
    float4 ma = *(const float4*)(x_maa + d);
    float4 sx, xx;
    sx.x = sh.x - xv.x; sx.y = sh.y - xv.y; sx.z = sh.z - xv.z; sx.w = sh.w - xv.w;
    xx.x = fmaf(sx.x, ma.x, xv.x); xx.y = fmaf(sx.y, ma.y, xv.y);
    xx.z = fmaf(sx.z, ma.z, xv.z); xx.w = fmaf(sx.w, ma.w, xv.w);
    *(float4*)(g_scratch + S_SX + idx)  = sx;
    *(float4*)(g_scratch + S_XXX + idx) = xx;
    if (t == T_ - 1)
        *(float4*)(xlast + (size_t)b * D_ + d) = xv;
}

// ---------------------------------------------------------------------------
// Weight transpose + bf16 split: T[n][k] = split(W[k][n])
// ---------------------------------------------------------------------------
__global__ __launch_bounds__(256) void wsplit_t(const float* __restrict__ W,
    __nv_bfloat16* __restrict__ Th, __nv_bfloat16* __restrict__ Tl)
{
    __shared__ float tile[32][33];
    int n0 = blockIdx.x * 32, k0 = blockIdx.y * 32;
    int tx = threadIdx.x & 31, ty0 = threadIdx.x >> 5;
    #pragma unroll
    for (int r = ty0; r < 32; r += 8)
        tile[r][tx] = W[(size_t)(k0 + r) * D_ + n0 + tx];
    __syncthreads();
    #pragma unroll
    for (int r = ty0; r < 32; r += 8) {
        float v = tile[tx][r];               // W[k0+tx][n0+r]
        __nv_bfloat16 h, l; split2(v, h, l);
        size_t o = (size_t)(n0 + r) * D_ + k0 + tx;
        Th[o] = h; Tl[o] = l;
    }
}

// ---------------------------------------------------------------------------
// Epilogues
// ---------------------------------------------------------------------------
enum { EPI_NONE = 0, EPI_TANH, EPI_SIG, EPI_SILU, EPI_BLEND, EPI_WDECAY };

template<int EPI>
__device__ __forceinline__ float epi_apply(float v, size_t idx, int col,
    const float* e1, const float* e2, const float* e3)
{
    if (EPI == EPI_TANH)   return tanhf(v);
    if (EPI == EPI_SIG)    return 1.f / (1.f + expf(-v));
    if (EPI == EPI_SILU)   return v / (1.f + expf(-v));
    if (EPI == EPI_BLEND)  return fmaf(e2[idx], e3[col] + v, e1[idx]);
    if (EPI == EPI_WDECAY) return expf(-expf(v + e3[col]));
    return v;
}

// ---------------------------------------------------------------------------
// FFMA GEMM (fp32 or bf16-pair out) with fused epilogues — small-K/N paths.
// ---------------------------------------------------------------------------
template<int EPI, int BOUT>
__global__ __launch_bounds__(256)
void sgemm_k(const float* __restrict__ A, int lda,
             const float* __restrict__ Bg, int ldb,
             void* __restrict__ Cv, void* __restrict__ Clv, int ldc,
             int N, int K,
             const float* __restrict__ e1, const float* __restrict__ e2,
             const float* __restrict__ e3)
{
    __shared__ __align__(16) float As[16][132];
    __shared__ __align__(16) float Bs[16][128];

    const int tid = threadIdx.x;
    const int rowBase = blockIdx.y * 128;
    const int colBase = blockIdx.x * 128;

    const int a_row = tid >> 2;
    const int a_k   = (tid & 3) * 4;
    const int b_k   = tid >> 5;
    const int b_c   = (tid & 31) * 4;
    const int tx = tid & 15, ty = tid >> 4;

    float acc[8][8];
    #pragma unroll
    for (int i = 0; i < 8; i++)
        #pragma unroll
        for (int j = 0; j < 8; j++) acc[i][j] = 0.f;

    const int ktiles = K >> 4;
    const bool bok = (colBase + b_c) < N;
    const float4 zf4 = make_float4(0.f, 0.f, 0.f, 0.f);

    const float* Ag0 = A + (size_t)(rowBase + a_row) * lda + a_k;
    const float* Ag1 = Ag0 + (size_t)64 * lda;
    const float* Bg0 = Bg + (size_t)b_k * ldb + colBase + b_c;
    const float* Bg1 = Bg0 + (size_t)8 * ldb;

    float4 pa0 = *(const float4*)Ag0;
    float4 pa1 = *(const float4*)Ag1;
    float4 pb0 = bok ? *(const float4*)Bg0 : zf4;
    float4 pb1 = bok ? *(const float4*)Bg1 : zf4;

    for (int kt = 0; kt < ktiles; ++kt) {
        As[a_k + 0][a_row]      = pa0.x; As[a_k + 1][a_row]      = pa0.y;
        As[a_k + 2][a_row]      = pa0.z; As[a_k + 3][a_row]      = pa0.w;
        As[a_k + 0][a_row + 64] = pa1.x; As[a_k + 1][a_row + 64] = pa1.y;
        As[a_k + 2][a_row + 64] = pa1.z; As[a_k + 3][a_row + 64] = pa1.w;
        *(float4*)&Bs[b_k][b_c]     = pb0;
        *(float4*)&Bs[b_k + 8][b_c] = pb1;
        __syncthreads();

        if (kt + 1 < ktiles) {
            pa0 = *(const float4*)(Ag0 + (size_t)(kt + 1) * 16);
            pa1 = *(const float4*)(Ag1 + (size_t)(kt + 1) * 16);
            pb0 = bok ? *(const float4*)(Bg0 + (size_t)(kt + 1) * 16 * ldb) : zf4;
            pb1 = bok ? *(const float4*)(Bg1 + (size_t)(kt + 1) * 16 * ldb) : zf4;
        }

        #pragma unroll
        for (int kk = 0; kk < 16; ++kk) {
            float4 a0 = *(const float4*)&As[kk][ty * 4];
            float4 a1 = *(const float4*)&As[kk][ty * 4 + 64];
            float4 b0 = *(const float4*)&Bs[kk][tx * 4];
            float4 b1 = *(const float4*)&Bs[kk][tx * 4 + 64];
            float av[8] = {a0.x, a0.y, a0.z, a0.w, a1.x, a1.y, a1.z, a1.w};
            float bv[8] = {b0.x, b0.y, b0.z, b0.w, b1.x, b1.y, b1.z, b1.w};
            #pragma unroll
            for (int i = 0; i < 8; i++)
                #pragma unroll
                for (int j = 0; j < 8; j++)
                    acc[i][j] = fmaf(av[i], bv[j], acc[i][j]);
        }
        __syncthreads();
    }

    #pragma unroll
    for (int i = 0; i < 8; i++) {
        int r = rowBase + ty * 4 + (i & 3) + (i >> 2) * 64;
        #pragma unroll
        for (int jh = 0; jh < 2; jh++) {
            int c = colBase + tx * 4 + jh * 64;
            if (c < N) {
                size_t idx = (size_t)r * ldc + c;
                float o[4];
                #pragma unroll
                for (int q = 0; q < 4; q++)
                    o[q] = epi_apply<EPI>(acc[i][jh * 4 + q], idx + q, c + q, e1, e2, e3);
                if (BOUT == 0) {
                    float4 f4o = make_float4(o[0], o[1], o[2], o[3]);
                    *(float4*)((float*)Cv + idx) = f4o;
                } else {
                    union { __nv_bfloat16 b[4]; uint2 u; } ph, pl;
                    #pragma unroll
                    for (int q = 0; q < 4; q++) split2(o[q], ph.b[q], pl.b[q]);
                    *(uint2*)((__nv_bfloat16*)Cv + idx)  = ph.u;
                    *(uint2*)((__nv_bfloat16*)Clv + idx) = pl.u;
                }
            }
        }
    }
}

// ---------------------------------------------------------------------------
// Tensor-core GEMM via mma.sync bf16 3-term split:
//   C[8192,2048] = (Ahi+Alo)[M,K] @ ((Bhi+Blo)[N,K])^T, fp32 accumulate.
// CTA tile 128x128, BK=32, 8 warps (warp tile 64x32), 2-stage cp.async.
// smem rows padded to 80B (stride 20 banks -> conflict-free ldmatrix).
// ---------------------------------------------------------------------------
constexpr int TGP_ROWB  = 80;                 // bytes per smem row (32 bf16 + pad)
constexpr int TGP_TILE  = 128 * TGP_ROWB;     // 10240 B
constexpr int TGP_STAGE = 4 * TGP_TILE;       // Ahi, Alo, Bhi, Blo
constexpr int TGP_SMEM  = 2 * TGP_STAGE;      // 81920 B
constexpr int TGP_NKT   = D_ / 32;            // 64 k-iterations

template<int EPI>
__global__ __launch_bounds__(256, 1)
void tgemm_k(const __nv_bfloat16* __restrict__ Ahi, const __nv_bfloat16* __restrict__ Alo,
             const __nv_bfloat16* __restrict__ Bhi, const __nv_bfloat16* __restrict__ Blo,
             float* __restrict__ C)
{
    extern __shared__ __align__(16) char dsm[];
    const uint32_t sbase = smem_u32(dsm);

    const int tid  = threadIdx.x;
    const int wid  = tid >> 5;
    const int lane = tid & 31;
    const int rowBase = blockIdx.y * 128;
    const int colBase = blockIdx.x * 128;

    const int warpM = wid & 1;          // 0..1
    const int warpN = wid >> 1;         // 0..3

    // lane constants for ldmatrix addressing
    const int mi = lane >> 3, rr = lane & 7;
    const int aRow0   = warpM * 64 + (mi & 1) * 8 + rr;
    const int aColOff = (mi >> 1) * 8;
    const int bRow0   = warpN * 32 + (mi >> 1) * 8 + rr;
    const int bColOff = (mi & 1) * 8;

    const __nv_bfloat16* srcs[4] = {Ahi, Alo, Bhi, Blo};

    auto load_stage = [&](int kt, int s) {
        const uint32_t stg = sbase + s * TGP_STAGE;
        #pragma unroll
        for (int i = 0; i < 8; i++) {
            int c    = tid + i * 256;        // 0..2047
            int tile = c >> 9;               // 0..3
            int w    = c & 511;
            int row  = w >> 2;               // 0..127
            int kc   = w & 3;                // 16B chunk within 64B row
            uint32_t dst = stg + tile * TGP_TILE + row * TGP_ROWB + kc * 16;
            int gRow = ((tile < 2) ? rowBase : colBase) + row;
            const __nv_bfloat16* src = srcs[tile] + (size_t)gRow * D_ + kt * 32 + kc * 8;
            cp16(dst, src);
        }
        cp_commit();
    };

    float cfr[4][4][4];
    #pragma unroll
    for (int a = 0; a < 4; a++)
        #pragma unroll
        for (int b = 0; b < 4; b++)
            #pragma unroll
            for (int q = 0; q < 4; q++) cfr[a][b][q] = 0.f;

    load_stage(0, 0);
    load_stage(1, 1);

    for (int kt = 0; kt < TGP_NKT; ++kt) {
        const int s = kt & 1;
        if (kt + 1 < TGP_NKT) cp_wait1(); else cp_wait0();
        __syncthreads();

        const uint32_t stg = sbase + s * TGP_STAGE;
        #pragma unroll
        for (int ks = 0; ks < 2; ++ks) {
            uint32_t ah[4][4], al[4][4], bh[2][4], bl[2][4];
            #pragma unroll
            for (int mf = 0; mf < 4; mf++) {
                uint32_t ad = stg + (uint32_t)((aRow0 + mf * 16) * TGP_ROWB
                                               + (ks * 16 + aColOff) * 2);
                ldmx4(ah[mf], ad);
                ldmx4(al[mf], ad + TGP_TILE);
            }
            #pragma unroll
            for (int pf = 0; pf < 2; pf++) {
                uint32_t bd = stg + 2 * TGP_TILE
                            + (uint32_t)((bRow0 + pf * 16) * TGP_ROWB
                                         + (ks * 16 + bColOff) * 2);
                ldmx4(bh[pf], bd);
                ldmx4(bl[pf], bd + TGP_TILE);
            }
            #pragma unroll
            for (int mf = 0; mf < 4; mf++)
                #pragma unroll
                for (int nf = 0; nf < 4; nf++) {
                    uint32_t b0h = bh[nf >> 1][(nf & 1) * 2];
                    uint32_t b1h = bh[nf >> 1][(nf & 1) * 2 + 1];
                    uint32_t b0l = bl[nf >> 1][(nf & 1) * 2];
                    uint32_t b1l = bl[nf >> 1][(nf & 1) * 2 + 1];
                    mma16816(cfr[mf][nf], ah[mf], b0h, b1h);
                    mma16816(cfr[mf][nf], ah[mf], b0l, b1l);
                    mma16816(cfr[mf][nf], al[mf], b0h, b1h);
                }
        }
        __syncthreads();
        if (kt + 2 < TGP_NKT) load_stage(kt + 2, s);
    }

    // epilogue: direct float2 stores
    const int cRow = lane >> 2;
    const int cCol = (lane & 3) * 2;
    #pragma unroll
    for (int mf = 0; mf < 4; mf++) {
        int r0 = rowBase + warpM * 64 + mf * 16 + cRow;
        #pragma unroll
        for (int nf = 0; nf < 4; nf++) {
            int cc = colBase + warpN * 32 + nf * 8 + cCol;
            float* p0 = C + (size_t)r0 * D_ + cc;
            float* p1 = p0 + (size_t)8 * D_;
            float2 o0, o1;
            o0.x = epi_apply<EPI>(cfr[mf][nf][0], 0, 0, nullptr, nullptr, nullptr);
            o0.y = epi_apply<EPI>(cfr[mf][nf][1], 0, 0, nullptr, nullptr, nullptr);
            o1.x = epi_apply<EPI>(cfr[mf][nf][2], 0, 0, nullptr, nullptr, nullptr);
            o1.y = epi_apply<EPI>(cfr[mf][nf][3], 0, 0, nullptr, nullptr, nullptr);
            *(float2*)p0 = o0;
            *(float2*)p1 = o1;
        }
    }
}

// ---------------------------------------------------------------------------
// WKV scan
// ---------------------------------------------------------------------------
constexpr int WKV_CH = 32;

__global__ __launch_bounds__(256) void wkv_kernel(
    const float* __restrict__ u, const float* __restrict__ state_in,
    float* __restrict__ state_out)
{
    const float* r = g_scratch + S_R;
    const float* k = g_scratch + S_K;
    const float* v = g_scratch + S_V;
    const float* w = g_scratch + S_W;
    float*       o = g_scratch + S_WKV;

    int bh = blockIdx.x;
    int b = bh / H_, h = bh % H_;
    int tid = threadIdx.x;
    int j = tid >> 2, q = tid & 3;

    float st[16], uu[16];
    const float* sin = state_in + (size_t)bh * HS_ * HS_;
    #pragma unroll
    for (int ii = 0; ii < 16; ii++) {
        int i = ii * 4 + q;
        st[ii] = sin[i * HS_ + j];
        uu[ii] = u[h * HS_ + i];
    }

    __shared__ __align__(16) float sr[WKV_CH][64];
    __shared__ __align__(16) float sk[WKV_CH][64];
    __shared__ __align__(16) float sv[WKV_CH][64];
    __shared__ __align__(16) float sw[WKV_CH][64];

    size_t rowBase = (size_t)(b * T_) * D_ + h * HS_;

    for (int t0 = 0; t0 < T_; t0 += WKV_CH) {
        __syncthreads();
        #pragma unroll
        for (int l = 0; l < 2; l++) {
            int f4 = tid + l * 256;
            int s  = f4 >> 4;
            int c  = (f4 & 15) * 4;
            size_t g = rowBase + (size_t)(t0 + s) * D_ + c;
            *(float4*)&sr[s][c] = *(const float4*)(r + g);
            *(float4*)&sk[s][c] = *(const float4*)(k + g);
            *(float4*)&sv[s][c] = *(const float4*)(v + g);
            *(float4*)&sw[s][c] = *(const float4*)(w + g);
        }
        __syncthreads();

        for (int s = 0; s < WKV_CH; s++) {
            float vj = sv[s][j];
            float acc = 0.f, acc2 = 0.f;
            #pragma unroll
            for (int ii = 0; ii < 16; ii++) {
                int i = ii * 4 + q;
                float ri = sr[s][i], ki = sk[s][i], wi = sw[s][i];
                acc  = fmaf(ri, st[ii], acc);
                acc2 = fmaf(ri * ki, uu[ii], acc2);
                st[ii] = fmaf(st[ii], wi, ki * vj);
            }
            acc  += __shfl_xor_sync(0xffffffffu, acc, 1);
            acc  += __shfl_xor_sync(0xffffffffu, acc, 2);
            acc2 += __shfl_xor_sync(0xffffffffu, acc2, 1);
            acc2 += __shfl_xor_sync(0xffffffffu, acc2, 2);
            if (q == 0)
                o[rowBase + (size_t)(t0 + s) * D_ + j] = fmaf(vj, acc2, acc);
        }
    }

    float* sout = state_out + (size_t)bh * HS_ * HS_;
    #pragma unroll
    for (int ii = 0; ii < 16; ii++)
        sout[(ii * 4 + q) * HS_ + j] = st[ii];
}

// ---------------------------------------------------------------------------
// GroupNorm + ln + gate multiply → bf16 hi/lo pair (feeds W_o tensor GEMM)
// ---------------------------------------------------------------------------
__global__ __launch_bounds__(256) void gnorm_kernel(
    const float* __restrict__ lng, const float* __restrict__ lnb)
{
    const float* wkv  = g_scratch + S_WKV;
    const float* gate = g_scratch + S_GATE;
    __nv_bfloat16* oh = g_bf + B_GGH;
    __nv_bfloat16* ol = g_bf + B_GGL;

    int gid  = blockIdx.x * 8 + (threadIdx.x >> 5);
    int lane = threadIdx.x & 31;
    size_t base = (size_t)gid * 64;

    float v0 = wkv[base + lane], v1 = wkv[base + 32 + lane];
    float s = v0 + v1, ss = v0 * v0 + v1 * v1;
    #pragma unroll
    for (int off = 16; off > 0; off >>= 1) {
        s  += __shfl_xor_sync(0xffffffffu, s, off);
        ss += __shfl_xor_sync(0xffffffffu, ss, off);
    }
    float mu   = s * (1.f / 64.f);
    float var  = ss * (1.f / 64.f) - mu * mu;
    float rstd = rsqrtf(var + 1e-5f);

    int h  = gid & (H_ - 1);
    int d0 = h * 64 + lane, d1 = d0 + 32;
    float o0 = fmaf((v0 - mu) * rstd, lng[d0], lnb[d0]) * gate[base + lane];
    float o1 = fmaf((v1 - mu) * rstd, lng[d1], lnb[d1]) * gate[base + 32 + lane];
    __nv_bfloat16 h0, l0, h1, l1;
    split2(o0, h0, l0); split2(o1, h1, l1);
    oh[base + lane] = h0;      ol[base + lane] = l0;
    oh[base + 32 + lane] = h1; ol[base + 32 + lane] = l1;
}

// ---------------------------------------------------------------------------
// Launch
// ---------------------------------------------------------------------------
extern "C" void kernel_launch(void* const* d_in, const int* in_sizes, int n_in,
                              void* d_out, int out_size)
{
    const float* x     = (const float*)d_in[0];
    const float* prev  = (const float*)d_in[1];
    const float* st0   = (const float*)d_in[2];
    const float* x_maa = (const float*)d_in[3];
    const float* w_maa = (const float*)d_in[4];
    const float* k_maa = (const float*)d_in[5];
    const float* v_maa = (const float*)d_in[6];
    const float* r_maa = (const float*)d_in[7];
    const float* g_maa = (const float*)d_in[8];
    const float* tm_w1 = (const float*)d_in[9];
    const float* tm_w2 = (const float*)d_in[10];
    const float* td_w1 = (const float*)d_in[11];
    const float* td_w2 = (const float*)d_in[12];
    const float* decay = (const float*)d_in[13];
    const float* first = (const float*)d_in[14];
    const float* W_r   = (const float*)d_in[15];
    const float* W_k   = (const float*)d_in[16];
    const float* W_v   = (const float*)d_in[17];
    const float* W_g   = (const float*)d_in[18];
    const float* W_o   = (const float*)d_in[19];
    const float* ln_g  = (const float*)d_in[20];
    const float* ln_b  = (const float*)d_in[21];

    float* out       = (float*)d_out;
    float* out_xlast = out + BTD_;
    float* out_state = out + BTD_ + (size_t)B_ * D_;

    float* S = nullptr;
    cudaGetSymbolAddress((void**)&S, g_scratch);
    __nv_bfloat16* Bf = nullptr;
    cudaGetSymbolAddress((void**)&Bf, g_bf);

    // idempotent, capture-safe host-side config
    cudaFuncSetAttribute(tgemm_k<EPI_NONE>, cudaFuncAttributeMaxDynamicSharedMemorySize, TGP_SMEM);
    cudaFuncSetAttribute(tgemm_k<EPI_SIG>,  cudaFuncAttributeMaxDynamicSharedMemorySize, TGP_SMEM);
    cudaFuncSetAttribute(tgemm_k<EPI_SILU>, cudaFuncAttributeMaxDynamicSharedMemorySize, TGP_SMEM);

    dim3 blk(256);
    dim3 tgrid(16, 64);       // tensor GEMM: N/128 x M/128
    dim3 wtg(64, 64);         // weight transpose

    // 0) weight transpose + split (independent of activations)
    wsplit_t<<<wtg, blk>>>(W_r, Bf + B_WT0 + 0 * WSEG, Bf + B_WT0 + 1 * WSEG);
    wsplit_t<<<wtg, blk>>>(W_k, Bf + B_WT0 + 2 * WSEG, Bf + B_WT0 + 3 * WSEG);
    wsplit_t<<<wtg, blk>>>(W_v, Bf + B_WT0 + 4 * WSEG, Bf + B_WT0 + 5 * WSEG);
    wsplit_t<<<wtg, blk>>>(W_g, Bf + B_WT0 + 6 * WSEG, Bf + B_WT0 + 7 * WSEG);
    wsplit_t<<<wtg, blk>>>(W_o, Bf + B_WT0 + 8 * WSEG, Bf + B_WT0 + 9 * WSEG);

    // 1) shift / sx / xxx / x_last
    prep_kernel<<<(unsigned)(BTD_ / 4 / 256), blk>>>(x, prev, x_maa, out_xlast);

    // 2) m = tanh(xxx @ tm_w1)
    sgemm_k<EPI_TANH, 0><<<dim3(2, BT_ / 128), blk>>>(
        S + S_XXX, D_, tm_w1, E5_, S + S_M, nullptr, E5_, E5_, D_,
        nullptr, nullptr, nullptr);

    // 3) token-mix blends
    dim3 full(16, BT_ / 128);
    // wx stays fp32 (feeds td path)
    sgemm_k<EPI_BLEND, 0><<<full, blk>>>(
        S + S_M + 0 * 32, E5_, tm_w2 + (size_t)0 * 32 * D_, D_,
        S + S_WX, nullptr, D_, D_, 32, x, S + S_SX, w_maa);
    // kx, vx, rx, gx as bf16 hi/lo pairs
    sgemm_k<EPI_BLEND, 1><<<full, blk>>>(
        S + S_M + 1 * 32, E5_, tm_w2 + (size_t)1 * 32 * D_, D_,
        Bf + B_KXH, Bf + B_KXL, D_, D_, 32, x, S + S_SX, k_maa);
    sgemm_k<EPI_BLEND, 1><<<full, blk>>>(
        S + S_M + 2 * 32, E5_, tm_w2 + (size_t)2 * 32 * D_, D_,
        Bf + B_VXH, Bf + B_VXL, D_, D_, 32, x, S + S_SX, v_maa);
    sgemm_k<EPI_BLEND, 1><<<full, blk>>>(
        S + S_M + 3 * 32, E5_, tm_w2 + (size_t)3 * 32 * D_, D_,
        Bf + B_RXH, Bf + B_RXL, D_, D_, 32, x, S + S_SX, r_maa);
    sgemm_k<EPI_BLEND, 1><<<full, blk>>>(
        S + S_M + 4 * 32, E5_, tm_w2 + (size_t)4 * 32 * D_, D_,
        Bf + B_GXH, Bf + B_GXL, D_, D_, 32, x, S + S_SX, g_maa);

    // 4) projections on tensor cores (bf16 split x3 mma.sync, fp32 accumulate)
    tgemm_k<EPI_SIG><<<tgrid, blk, TGP_SMEM>>>(
        Bf + B_RXH, Bf + B_RXL, Bf + B_WT0 + 0 * WSEG, Bf + B_WT0 + 1 * WSEG, S + S_R);
    tgemm_k<EPI_NONE><<<tgrid, blk, TGP_SMEM>>>(
        Bf + B_KXH, Bf + B_KXL, Bf + B_WT0 + 2 * WSEG, Bf + B_WT0 + 3 * WSEG, S + S_K);
    tgemm_k<EPI_NONE><<<tgrid, blk, TGP_SMEM>>>(
        Bf + B_VXH, Bf + B_VXL, Bf + B_WT0 + 4 * WSEG, Bf + B_WT0 + 5 * WSEG, S + S_V);
    tgemm_k<EPI_SILU><<<tgrid, blk, TGP_SMEM>>>(
        Bf + B_GXH, Bf + B_GXL, Bf + B_WT0 + 6 * WSEG, Bf + B_WT0 + 7 * WSEG, S + S_GATE);

    // 5) decay path (FFMA; small)
    sgemm_k<EPI_TANH, 0><<<dim3(1, BT_ / 128), blk>>>(
        S + S_WX, D_, td_w1, TD_, S + S_WTMP, nullptr, TD_, TD_, D_,
        nullptr, nullptr, nullptr);
    sgemm_k<EPI_WDECAY, 0><<<full, blk>>>(
        S + S_WTMP, TD_, td_w2, D_, S + S_W, nullptr, D_, D_, TD_,
        nullptr, nullptr, decay);

    // 6) WKV scan
    wkv_kernel<<<B_ * H_, blk>>>(first, st0, out_state);

    // 7) groupnorm + gate → gg (bf16 pair)
    gnorm_kernel<<<BT_ * H_ / 8, blk>>>(ln_g, ln_b);

    // 8) final projection on tensor cores
    tgemm_k<EPI_NONE><<<tgrid, blk, TGP_SMEM>>>(
        Bf + B_GGH, Bf + B_GGL, Bf + B_WT0 + 8 * WSEG, Bf + B_WT0 + 9 * WSEG, out);
}

// round 5
// speedup vs baseline: 2.4239x; 1.2027x over previous
#include <cuda_runtime.h>
#include <cuda_bf16.h>
#include <math.h>
#include <stdint.h>

// ---------------------------------------------------------------------------
// Problem constants
// ---------------------------------------------------------------------------
namespace {
constexpr int B_ = 4, T_ = 2048, D_ = 2048, H_ = 32, HS_ = 64;
constexpr int BT_ = B_ * T_;            // 8192
constexpr int E5_ = 160, TD_ = 64;
constexpr long long BTD_ = (long long)BT_ * D_;   // 16,777,216

// fp32 scratch segments
constexpr size_t SEG = (size_t)BT_ * D_;
constexpr size_t S_SX   = 0;
constexpr size_t S_R    = 1 * SEG;
constexpr size_t S_K    = 2 * SEG;
constexpr size_t S_V    = 3 * SEG;
constexpr size_t S_GATE = 4 * SEG;
constexpr size_t S_W    = 5 * SEG;
constexpr size_t S_WKV  = 6 * SEG;
constexpr size_t S_M    = 7 * SEG;                    // 8192 x 160 fp32
constexpr size_t SCRATCH_FLOATS = S_M + (size_t)BT_ * E5_;

// bf16 scratch segments
constexpr size_t WSEG = (size_t)D_ * D_;
constexpr size_t B_XXH = 0,         B_XXL = 1 * SEG;
constexpr size_t B_WXH = 2 * SEG,   B_WXL = 3 * SEG;
constexpr size_t B_KXH = 4 * SEG,   B_KXL = 5 * SEG;
constexpr size_t B_VXH = 6 * SEG,   B_VXL = 7 * SEG;
constexpr size_t B_RXH = 8 * SEG,   B_RXL = 9 * SEG;
constexpr size_t B_GXH = 10 * SEG,  B_GXL = 11 * SEG;
constexpr size_t B_GGH = 12 * SEG,  B_GGL = 13 * SEG;
constexpr size_t B_WT0 = 14 * SEG;                    // 10 weight segs (W_r..W_o hi/lo)
constexpr size_t B_TM1H = B_WT0 + 10 * WSEG;          // 256 x 2048
constexpr size_t B_TM1L = B_TM1H + (size_t)256 * D_;
constexpr size_t B_TD1H = B_TM1L + (size_t)256 * D_;  // 128 x 2048
constexpr size_t B_TD1L = B_TD1H + (size_t)128 * D_;
constexpr size_t B_TD2H = B_TD1L + (size_t)128 * D_;  // 2048 x 64
constexpr size_t B_TD2L = B_TD2H + (size_t)D_ * 64;
constexpr size_t B_HH   = B_TD2L + (size_t)D_ * 64;   // 8192 x 64
constexpr size_t B_HL   = B_HH + (size_t)BT_ * 64;
constexpr size_t BF_TOTAL = B_HL + (size_t)BT_ * 64;
}

__device__ __align__(256) float g_scratch[SCRATCH_FLOATS];
__device__ __align__(256) __nv_bfloat16 g_bf[BF_TOTAL];

// ---------------------------------------------------------------------------
// PTX helpers (plain compute_80-level PTX — no arch-'a' features)
// ---------------------------------------------------------------------------
__device__ __forceinline__ uint32_t smem_u32(const void* p) {
    uint32_t a;
    asm("{ .reg .u64 t; cvta.to.shared.u64 t, %1; cvt.u32.u64 %0, t; }"
        : "=r"(a) : "l"(p));
    return a;
}

__device__ __forceinline__ void cp16(uint32_t saddr, const void* g) {
    asm volatile("cp.async.cg.shared.global [%0], [%1], 16;" :: "r"(saddr), "l"(g));
}
__device__ __forceinline__ void cp_commit() { asm volatile("cp.async.commit_group;" ::: "memory"); }
__device__ __forceinline__ void cp_wait1() { asm volatile("cp.async.wait_group 1;" ::: "memory"); }
__device__ __forceinline__ void cp_wait0() { asm volatile("cp.async.wait_group 0;" ::: "memory"); }

__device__ __forceinline__ void ldmx4(uint32_t* r, uint32_t addr) {
    asm volatile("ldmatrix.sync.aligned.m8n8.x4.shared.b16 {%0,%1,%2,%3}, [%4];"
        : "=r"(r[0]), "=r"(r[1]), "=r"(r[2]), "=r"(r[3]) : "r"(addr));
}

__device__ __forceinline__ void mma16816(float* c, const uint32_t* a,
                                         uint32_t b0, uint32_t b1) {
    asm volatile(
        "mma.sync.aligned.m16n8k16.row.col.f32.bf16.bf16.f32 "
        "{%0,%1,%2,%3}, {%4,%5,%6,%7}, {%8,%9}, {%0,%1,%2,%3};"
        : "+f"(c[0]), "+f"(c[1]), "+f"(c[2]), "+f"(c[3])
        : "r"(a[0]), "r"(a[1]), "r"(a[2]), "r"(a[3]), "r"(b0), "r"(b1));
}

__device__ __forceinline__ void split2(float v, __nv_bfloat16& h, __nv_bfloat16& l) {
    h = __float2bfloat16(v);
    l = __float2bfloat16(v - __bfloat162float(h));
}

// ---------------------------------------------------------------------------
// Epilogues
// ---------------------------------------------------------------------------
enum { EPI_NONE = 0, EPI_TANH, EPI_SIG, EPI_SILU, EPI_WDECAY };

template<int EPI>
__device__ __forceinline__ float epi_apply(float v, int col, const float* e3)
{
    if (EPI == EPI_TANH)   return tanhf(v);
    if (EPI == EPI_SIG)    return 1.f / (1.f + expf(-v));
    if (EPI == EPI_SILU)   return v / (1.f + expf(-v));
    if (EPI == EPI_WDECAY) return expf(-expf(v + e3[col]));
    return v;
}

// ---------------------------------------------------------------------------
// prep: sx = shift(x) - x (fp32) ; xxx = x + sx*x_maa (bf16 pair) ; x_last
// ---------------------------------------------------------------------------
__global__ __launch_bounds__(256) void prep_kernel(
    const float* __restrict__ x, const float* __restrict__ prev,
    const float* __restrict__ x_maa, float* __restrict__ xlast)
{
    size_t i4 = (size_t)blockIdx.x * 256 + threadIdx.x;
    if (i4 >= (size_t)(BTD_ / 4)) return;
    size_t idx = i4 * 4;
    int d = (int)(idx % D_);
    size_t bt = idx / D_;
    int t = (int)(bt % T_);
    int b = (int)(bt / T_);

    float4 xv = *(const float4*)(x + idx);
    float4 sh = (t > 0) ? *(const float4*)(x + idx - D_)
                        : *(const float4*)(prev + (size_t)b * D_ + d);
    float4 ma = *(const float4*)(x_maa + d);
    float4 sx;
    sx.x = sh.x - xv.x; sx.y = sh.y - xv.y; sx.z = sh.z - xv.z; sx.w = sh.w - xv.w;
    float xx[4] = { fmaf(sx.x, ma.x, xv.x), fmaf(sx.y, ma.y, xv.y),
                    fmaf(sx.z, ma.z, xv.z), fmaf(sx.w, ma.w, xv.w) };
    *(float4*)(g_scratch + S_SX + idx) = sx;
    union { __nv_bfloat16 b[4]; uint2 u; } ph, pl;
    #pragma unroll
    for (int q = 0; q < 4; q++) split2(xx[q], ph.b[q], pl.b[q]);
    *(uint2*)(g_bf + B_XXH + idx) = ph.u;
    *(uint2*)(g_bf + B_XXL + idx) = pl.u;
    if (t == T_ - 1)
        *(float4*)(xlast + (size_t)b * D_ + d) = xv;
}

// ---------------------------------------------------------------------------
// Weight transpose + bf16 split with padding:
//   in  W[KK][NN] row-major, out T[n][k] (ld=KK) for n < NPAD, zero for n>=NN.
// grid (NPAD/32, KK/32), 256 threads.
// ---------------------------------------------------------------------------
__global__ __launch_bounds__(256) void wsplit_t(const float* __restrict__ W,
    int NN, int KK, __nv_bfloat16* __restrict__ Th, __nv_bfloat16* __restrict__ Tl)
{
    __shared__ float tile[32][33];
    int n0 = blockIdx.x * 32, k0 = blockIdx.y * 32;
    int tx = threadIdx.x & 31, ty0 = threadIdx.x >> 5;
    #pragma unroll
    for (int r = ty0; r < 32; r += 8)
        tile[r][tx] = (n0 + tx < NN) ? W[(size_t)(k0 + r) * NN + n0 + tx] : 0.f;
    __syncthreads();
    #pragma unroll
    for (int r = ty0; r < 32; r += 8) {
        float v = tile[tx][r];               // W[k0+tx][n0+r] (0 if padded)
        __nv_bfloat16 h, l; split2(v, h, l);
        size_t o = (size_t)(n0 + r) * KK + k0 + tx;
        Th[o] = h; Tl[o] = l;
    }
}

// ---------------------------------------------------------------------------
// Tensor-core GEMM (mma.sync bf16 3-term split), generalized:
//   C[M x Nvalid] = (Ahi+Alo)[M,K] @ ((Bhi+Blo)[Ncta,K])^T, fp32 accum.
// CTA tile 128x128, 4 warps (warp tile 64x64), BK=32, 2-stage cp.async.
// BOUT: 0 = fp32 C, 1 = bf16 hi/lo pair C.
// ---------------------------------------------------------------------------
constexpr int TGP_ROWB  = 80;                 // 32 bf16 + 16B pad
constexpr int TGP_TILE  = 128 * TGP_ROWB;     // 10240 B
constexpr int TGP_STAGE = 4 * TGP_TILE;       // Ahi, Alo, Bhi, Blo
constexpr int TGP_SMEM  = 2 * TGP_STAGE;      // 81920 B

template<int EPI, int BOUT>
__global__ __launch_bounds__(128, 2)
void tgemm_k(const __nv_bfloat16* __restrict__ Ahi, const __nv_bfloat16* __restrict__ Alo,
             int lda,
             const __nv_bfloat16* __restrict__ Bhi, const __nv_bfloat16* __restrict__ Blo,
             int ldb,
             void* __restrict__ Cv, void* __restrict__ Clv, int ldc,
             int nkt, int Nvalid, const float* __restrict__ e3)
{
    extern __shared__ __align__(16) char dsm[];
    const uint32_t sbase = smem_u32(dsm);

    const int tid  = threadIdx.x;
    const int wid  = tid >> 5;
    const int lane = tid & 31;
    const int rowBase = blockIdx.y * 128;
    const int colBase = blockIdx.x * 128;

    const int warpM = wid & 1;
    const int warpN = wid >> 1;

    const int mi = lane >> 3, rr = lane & 7;
    const int aRow0   = warpM * 64 + (mi & 1) * 8 + rr;
    const int aColOff = (mi >> 1) * 8;
    const int bRow0   = warpN * 64 + (mi >> 1) * 8 + rr;
    const int bColOff = (mi & 1) * 8;

    const __nv_bfloat16* srcs[4] = {Ahi, Alo, Bhi, Blo};

    auto load_stage = [&](int kt, int s) {
        const uint32_t stg = sbase + s * TGP_STAGE;
        #pragma unroll
        for (int i = 0; i < 16; i++) {
            int c    = tid + i * 128;        // 0..2047
            int tile = c >> 9;               // 0..3
            int w    = c & 511;
            int row  = w >> 2;               // 0..127
            int kc   = w & 3;
            uint32_t dst = stg + tile * TGP_TILE + row * TGP_ROWB + kc * 16;
            int gRow = ((tile < 2) ? rowBase : colBase) + row;
            int ld   = (tile < 2) ? lda : ldb;
            const __nv_bfloat16* src = srcs[tile] + (size_t)gRow * ld + kt * 32 + kc * 8;
            cp16(dst, src);
        }
        cp_commit();
    };

    float cfr[4][8][4];
    #pragma unroll
    for (int a = 0; a < 4; a++)
        #pragma unroll
        for (int b = 0; b < 8; b++)
            #pragma unroll
            for (int q = 0; q < 4; q++) cfr[a][b][q] = 0.f;

    load_stage(0, 0);
    load_stage(1, 1);

    for (int kt = 0; kt < nkt; ++kt) {
        const int s = kt & 1;
        if (kt + 1 < nkt) cp_wait1(); else cp_wait0();
        __syncthreads();

        const uint32_t stg = sbase + s * TGP_STAGE;
        #pragma unroll
        for (int ks = 0; ks < 2; ++ks) {
            uint32_t bh[4][4], bl[4][4];
            #pragma unroll
            for (int pf = 0; pf < 4; pf++) {
                uint32_t bd = stg + 2 * TGP_TILE
                            + (uint32_t)((bRow0 + pf * 16) * TGP_ROWB
                                         + (ks * 16 + bColOff) * 2);
                ldmx4(bh[pf], bd);
                ldmx4(bl[pf], bd + TGP_TILE);
            }
            #pragma unroll
            for (int mf = 0; mf < 4; mf++) {
                uint32_t ah[4], al[4];
                uint32_t ad = stg + (uint32_t)((aRow0 + mf * 16) * TGP_ROWB
                                               + (ks * 16 + aColOff) * 2);
                ldmx4(ah, ad);
                ldmx4(al, ad + TGP_TILE);
                #pragma unroll
                for (int nf = 0; nf < 8; nf++) {
                    uint32_t b0h = bh[nf >> 1][(nf & 1) * 2];
                    uint32_t b1h = bh[nf >> 1][(nf & 1) * 2 + 1];
                    uint32_t b0l = bl[nf >> 1][(nf & 1) * 2];
                    uint32_t b1l = bl[nf >> 1][(nf & 1) * 2 + 1];
                    mma16816(cfr[mf][nf], ah, b0h, b1h);
                    mma16816(cfr[mf][nf], ah, b0l, b1l);
                    mma16816(cfr[mf][nf], al, b0h, b1h);
                }
            }
        }
        __syncthreads();
        if (kt + 2 < nkt) load_stage(kt + 2, s);
    }

    // epilogue
    const int cRow = lane >> 2;
    const int cCol = (lane & 3) * 2;
    #pragma unroll
    for (int mf = 0; mf < 4; mf++) {
        int r0 = rowBase + warpM * 64 + mf * 16 + cRow;
        #pragma unroll
        for (int nf = 0; nf < 8; nf++) {
            int c = colBase + warpN * 64 + nf * 8 + cCol;
            if (c < Nvalid) {
                float v0 = epi_apply<EPI>(cfr[mf][nf][0], c,     e3);
                float v1 = epi_apply<EPI>(cfr[mf][nf][1], c + 1, e3);
                float v2 = epi_apply<EPI>(cfr[mf][nf][2], c,     e3);
                float v3 = epi_apply<EPI>(cfr[mf][nf][3], c + 1, e3);
                if (BOUT == 0) {
                    float* p0 = (float*)Cv + (size_t)r0 * ldc + c;
                    float* p1 = p0 + (size_t)8 * ldc;
                    *(float2*)p0 = make_float2(v0, v1);
                    *(float2*)p1 = make_float2(v2, v3);
                } else {
                    __nv_bfloat16 h0, l0, h1, l1;
                    __nv_bfloat162 ph, pl;
                    split2(v0, h0, l0); split2(v1, h1, l1);
                    ph.x = h0; ph.y = h1; pl.x = l0; pl.y = l1;
                    *(__nv_bfloat162*)((__nv_bfloat16*)Cv  + (size_t)r0 * ldc + c) = ph;
                    *(__nv_bfloat162*)((__nv_bfloat16*)Clv + (size_t)r0 * ldc + c) = pl;
                    split2(v2, h0, l0); split2(v3, h1, l1);
                    ph.x = h0; ph.y = h1; pl.x = l0; pl.y = l1;
                    *(__nv_bfloat162*)((__nv_bfloat16*)Cv  + (size_t)(r0 + 8) * ldc + c) = ph;
                    *(__nv_bfloat162*)((__nv_bfloat16*)Clv + (size_t)(r0 + 8) * ldc + c) = pl;
                }
            }
        }
    }
}

// ---------------------------------------------------------------------------
// Lean one-shot K=32 blend GEMM:
//   mix = A[M,32] @ B[32,N] ; out = x + sx*(maa + mix), written as bf16 pair.
// CTA tile 64x64, 256 threads (16x16 microtile of 4x4).
// ---------------------------------------------------------------------------
__global__ __launch_bounds__(256)
void blend_k(const float* __restrict__ A, int lda,
             const float* __restrict__ Bg, int ldb,
             const float* __restrict__ x, const float* __restrict__ sx,
             const float* __restrict__ maa,
             __nv_bfloat16* __restrict__ Oh, __nv_bfloat16* __restrict__ Ol)
{
    __shared__ __align__(16) float As[32][68];
    __shared__ __align__(16) float Bs[32][68];

    const int tid = threadIdx.x;
    const int rowBase = blockIdx.y * 64;
    const int colBase = blockIdx.x * 64;
    const int tx = tid & 15, ty = tid >> 4;

    // load A tile 64x32 (512 float4) and B tile 32x64 (512 float4)
    #pragma unroll
    for (int i = 0; i < 2; i++) {
        int f4 = tid + i * 256;
        int ar = f4 >> 3, ak = (f4 & 7) * 4;
        float4 av = *(const float4*)(A + (size_t)(rowBase + ar) * lda + ak);
        As[ak + 0][ar] = av.x; As[ak + 1][ar] = av.y;
        As[ak + 2][ar] = av.z; As[ak + 3][ar] = av.w;
        int br = f4 >> 4, bc = (f4 & 15) * 4;
        *(float4*)&Bs[br][bc] = *(const float4*)(Bg + (size_t)br * ldb + colBase + bc);
    }
    __syncthreads();

    float acc[4][4];
    #pragma unroll
    for (int i = 0; i < 4; i++)
        #pragma unroll
        for (int j = 0; j < 4; j++) acc[i][j] = 0.f;

    #pragma unroll
    for (int k = 0; k < 32; k++) {
        float4 a4 = *(const float4*)&As[k][ty * 4];
        float4 b4 = *(const float4*)&Bs[k][tx * 4];
        float av[4] = {a4.x, a4.y, a4.z, a4.w};
        float bv[4] = {b4.x, b4.y, b4.z, b4.w};
        #pragma unroll
        for (int i = 0; i < 4; i++)
            #pragma unroll
            for (int j = 0; j < 4; j++)
                acc[i][j] = fmaf(av[i], bv[j], acc[i][j]);
    }

    const int c = colBase + tx * 4;
    float4 ma = *(const float4*)(maa + c);
    #pragma unroll
    for (int i = 0; i < 4; i++) {
        int r = rowBase + ty * 4 + i;
        size_t idx = (size_t)r * D_ + c;
        float4 xv = *(const float4*)(x + idx);
        float4 sv = *(const float4*)(sx + idx);
        float o[4];
        o[0] = fmaf(sv.x, ma.x + acc[i][0], xv.x);
        o[1] = fmaf(sv.y, ma.y + acc[i][1], xv.y);
        o[2] = fmaf(sv.z, ma.z + acc[i][2], xv.z);
        o[3] = fmaf(sv.w, ma.w + acc[i][3], xv.w);
        union { __nv_bfloat16 b[4]; uint2 u; } ph, pl;
        #pragma unroll
        for (int q = 0; q < 4; q++) split2(o[q], ph.b[q], pl.b[q]);
        *(uint2*)(Oh + idx) = ph.u;
        *(uint2*)(Ol + idx) = pl.u;
    }
}

// ---------------------------------------------------------------------------
// WKV scan
// ---------------------------------------------------------------------------
constexpr int WKV_CH = 32;

__global__ __launch_bounds__(256) void wkv_kernel(
    const float* __restrict__ u, const float* __restrict__ state_in,
    float* __restrict__ state_out)
{
    const float* r = g_scratch + S_R;
    const float* k = g_scratch + S_K;
    const float* v = g_scratch + S_V;
    const float* w = g_scratch + S_W;
    float*       o = g_scratch + S_WKV;

    int bh = blockIdx.x;
    int b = bh / H_, h = bh % H_;
    int tid = threadIdx.x;
    int j = tid >> 2, q = tid & 3;

    float st[16], uu[16];
    const float* sin = state_in + (size_t)bh * HS_ * HS_;
    #pragma unroll
    for (int ii = 0; ii < 16; ii++) {
        int i = ii * 4 + q;
        st[ii] = sin[i * HS_ + j];
        uu[ii] = u[h * HS_ + i];
    }

    __shared__ __align__(16) float sr[WKV_CH][64];
    __shared__ __align__(16) float sk[WKV_CH][64];
    __shared__ __align__(16) float sv[WKV_CH][64];
    __shared__ __align__(16) float sw[WKV_CH][64];

    size_t rowBase = (size_t)(b * T_) * D_ + h * HS_;

    for (int t0 = 0; t0 < T_; t0 += WKV_CH) {
        __syncthreads();
        #pragma unroll
        for (int l = 0; l < 2; l++) {
            int f4 = tid + l * 256;
            int s  = f4 >> 4;
            int c  = (f4 & 15) * 4;
            size_t g = rowBase + (size_t)(t0 + s) * D_ + c;
            *(float4*)&sr[s][c] = *(const float4*)(r + g);
            *(float4*)&sk[s][c] = *(const float4*)(k + g);
            *(float4*)&sv[s][c] = *(const float4*)(v + g);
            *(float4*)&sw[s][c] = *(const float4*)(w + g);
        }
        __syncthreads();

        for (int s = 0; s < WKV_CH; s++) {
            float vj = sv[s][j];
            float acc = 0.f, acc2 = 0.f;
            #pragma unroll
            for (int ii = 0; ii < 16; ii++) {
                int i = ii * 4 + q;
                float ri = sr[s][i], ki = sk[s][i], wi = sw[s][i];
                acc  = fmaf(ri, st[ii], acc);
                acc2 = fmaf(ri * ki, uu[ii], acc2);
                st[ii] = fmaf(st[ii], wi, ki * vj);
            }
            acc  += __shfl_xor_sync(0xffffffffu, acc, 1);
            acc  += __shfl_xor_sync(0xffffffffu, acc, 2);
            acc2 += __shfl_xor_sync(0xffffffffu, acc2, 1);
            acc2 += __shfl_xor_sync(0xffffffffu, acc2, 2);
            if (q == 0)
                o[rowBase + (size_t)(t0 + s) * D_ + j] = fmaf(vj, acc2, acc);
        }
    }

    float* sout = state_out + (size_t)bh * HS_ * HS_;
    #pragma unroll
    for (int ii = 0; ii < 16; ii++)
        sout[(ii * 4 + q) * HS_ + j] = st[ii];
}

// ---------------------------------------------------------------------------
// GroupNorm + ln + gate multiply → bf16 hi/lo pair (feeds W_o tensor GEMM)
// ---------------------------------------------------------------------------
__global__ __launch_bounds__(256) void gnorm_kernel(
    const float* __restrict__ lng, const float* __restrict__ lnb)
{
    const float* wkv  = g_scratch + S_WKV;
    const float* gate = g_scratch + S_GATE;
    __nv_bfloat16* oh = g_bf + B_GGH;
    __nv_bfloat16* ol = g_bf + B_GGL;

    int gid  = blockIdx.x * 8 + (threadIdx.x >> 5);
    int lane = threadIdx.x & 31;
    size_t base = (size_t)gid * 64;

    float v0 = wkv[base + lane], v1 = wkv[base + 32 + lane];
    float s = v0 + v1, ss = v0 * v0 + v1 * v1;
    #pragma unroll
    for (int off = 16; off > 0; off >>= 1) {
        s  += __shfl_xor_sync(0xffffffffu, s, off);
        ss += __shfl_xor_sync(0xffffffffu, ss, off);
    }
    float mu   = s * (1.f / 64.f);
    float var  = ss * (1.f / 64.f) - mu * mu;
    float rstd = rsqrtf(var + 1e-5f);

    int h  = gid & (H_ - 1);
    int d0 = h * 64 + lane, d1 = d0 + 32;
    float o0 = fmaf((v0 - mu) * rstd, lng[d0], lnb[d0]) * gate[base + lane];
    float o1 = fmaf((v1 - mu) * rstd, lng[d1], lnb[d1]) * gate[base + 32 + lane];
    __nv_bfloat16 h0, l0, h1, l1;
    split2(o0, h0, l0); split2(o1, h1, l1);
    oh[base + lane] = h0;      ol[base + lane] = l0;
    oh[base + 32 + lane] = h1; ol[base + 32 + lane] = l1;
}

// ---------------------------------------------------------------------------
// Launch
// ---------------------------------------------------------------------------
extern "C" void kernel_launch(void* const* d_in, const int* in_sizes, int n_in,
                              void* d_out, int out_size)
{
    const float* x     = (const float*)d_in[0];
    const float* prev  = (const float*)d_in[1];
    const float* st0   = (const float*)d_in[2];
    const float* x_maa = (const float*)d_in[3];
    const float* w_maa = (const float*)d_in[4];
    const float* k_maa = (const float*)d_in[5];
    const float* v_maa = (const float*)d_in[6];
    const float* r_maa = (const float*)d_in[7];
    const float* g_maa = (const float*)d_in[8];
    const float* tm_w1 = (const float*)d_in[9];
    const float* tm_w2 = (const float*)d_in[10];
    const float* td_w1 = (const float*)d_in[11];
    const float* td_w2 = (const float*)d_in[12];
    const float* decay = (const float*)d_in[13];
    const float* first = (const float*)d_in[14];
    const float* W_r   = (const float*)d_in[15];
    const float* W_k   = (const float*)d_in[16];
    const float* W_v   = (const float*)d_in[17];
    const float* W_g   = (const float*)d_in[18];
    const float* W_o   = (const float*)d_in[19];
    const float* ln_g  = (const float*)d_in[20];
    const float* ln_b  = (const float*)d_in[21];

    float* out       = (float*)d_out;
    float* out_xlast = out + BTD_;
    float* out_state = out + BTD_ + (size_t)B_ * D_;

    float* S = nullptr;
    cudaGetSymbolAddress((void**)&S, g_scratch);
    __nv_bfloat16* Bf = nullptr;
    cudaGetSymbolAddress((void**)&Bf, g_bf);

    cudaFuncSetAttribute(tgemm_k<EPI_NONE,  0>, cudaFuncAttributeMaxDynamicSharedMemorySize, TGP_SMEM);
    cudaFuncSetAttribute(tgemm_k<EPI_SIG,   0>, cudaFuncAttributeMaxDynamicSharedMemorySize, TGP_SMEM);
    cudaFuncSetAttribute(tgemm_k<EPI_SILU,  0>, cudaFuncAttributeMaxDynamicSharedMemorySize, TGP_SMEM);
    cudaFuncSetAttribute(tgemm_k<EPI_TANH,  0>, cudaFuncAttributeMaxDynamicSharedMemorySize, TGP_SMEM);
    cudaFuncSetAttribute(tgemm_k<EPI_TANH,  1>, cudaFuncAttributeMaxDynamicSharedMemorySize, TGP_SMEM);
    cudaFuncSetAttribute(tgemm_k<EPI_WDECAY,0>, cudaFuncAttributeMaxDynamicSharedMemorySize, TGP_SMEM);

    dim3 blk(256);
    dim3 tblk(128);

    // 0) weight transpose + split
    wsplit_t<<<dim3(64, 64), blk>>>(W_r,   D_, D_, Bf + B_WT0 + 0 * WSEG, Bf + B_WT0 + 1 * WSEG);
    wsplit_t<<<dim3(64, 64), blk>>>(W_k,   D_, D_, Bf + B_WT0 + 2 * WSEG, Bf + B_WT0 + 3 * WSEG);
    wsplit_t<<<dim3(64, 64), blk>>>(W_v,   D_, D_, Bf + B_WT0 + 4 * WSEG, Bf + B_WT0 + 5 * WSEG);
    wsplit_t<<<dim3(64, 64), blk>>>(W_g,   D_, D_, Bf + B_WT0 + 6 * WSEG, Bf + B_WT0 + 7 * WSEG);
    wsplit_t<<<dim3(64, 64), blk>>>(W_o,   D_, D_, Bf + B_WT0 + 8 * WSEG, Bf + B_WT0 + 9 * WSEG);
    wsplit_t<<<dim3(8,  64), blk>>>(tm_w1, E5_, D_, Bf + B_TM1H, Bf + B_TM1L);   // pad 160->256
    wsplit_t<<<dim3(4,  64), blk>>>(td_w1, TD_, D_, Bf + B_TD1H, Bf + B_TD1L);   // pad 64->128
    wsplit_t<<<dim3(64, 2),  blk>>>(td_w2, D_,  TD_, Bf + B_TD2H, Bf + B_TD2L);  // [64][2048] -> [2048][64]

    // 1) prep
    prep_kernel<<<(unsigned)(BTD_ / 4 / 256), blk>>>(x, prev, x_maa, out_xlast);

    // 2) m = tanh(xxx @ tm_w1)   [8192 x 160] fp32
    tgemm_k<EPI_TANH, 0><<<dim3(2, 64), tblk, TGP_SMEM>>>(
        Bf + B_XXH, Bf + B_XXL, D_, Bf + B_TM1H, Bf + B_TM1L, D_,
        S + S_M, nullptr, E5_, D_ / 32, E5_, nullptr);

    // 3) five token-mix blends (lean K=32 GEMM + fused blend, bf16-pair out)
    const float* maas[5] = {w_maa, k_maa, v_maa, r_maa, g_maa};
    const size_t oh[5] = {B_WXH, B_KXH, B_VXH, B_RXH, B_GXH};
    const size_t ol[5] = {B_WXL, B_KXL, B_VXL, B_RXL, B_GXL};
    for (int f = 0; f < 5; ++f)
        blend_k<<<dim3(32, 128), blk>>>(
            S + S_M + f * 32, E5_, tm_w2 + (size_t)f * 32 * D_, D_,
            x, S + S_SX, maas[f], Bf + oh[f], Bf + ol[f]);

    // 4) projections (tensor)
    tgemm_k<EPI_SIG, 0><<<dim3(16, 64), tblk, TGP_SMEM>>>(
        Bf + B_RXH, Bf + B_RXL, D_, Bf + B_WT0 + 0 * WSEG, Bf + B_WT0 + 1 * WSEG, D_,
        S + S_R, nullptr, D_, D_ / 32, D_, nullptr);
    tgemm_k<EPI_NONE, 0><<<dim3(16, 64), tblk, TGP_SMEM>>>(
        Bf + B_KXH, Bf + B_KXL, D_, Bf + B_WT0 + 2 * WSEG, Bf + B_WT0 + 3 * WSEG, D_,
        S + S_K, nullptr, D_, D_ / 32, D_, nullptr);
    tgemm_k<EPI_NONE, 0><<<dim3(16, 64), tblk, TGP_SMEM>>>(
        Bf + B_VXH, Bf + B_VXL, D_, Bf + B_WT0 + 4 * WSEG, Bf + B_WT0 + 5 * WSEG, D_,
        S + S_V, nullptr, D_, D_ / 32, D_, nullptr);
    tgemm_k<EPI_SILU, 0><<<dim3(16, 64), tblk, TGP_SMEM>>>(
        Bf + B_GXH, Bf + B_GXL, D_, Bf + B_WT0 + 6 * WSEG, Bf + B_WT0 + 7 * WSEG, D_,
        S + S_GATE, nullptr, D_, D_ / 32, D_, nullptr);

    // 5) decay path (tensor): h = tanh(wx @ td_w1) as bf16 pair, then
    //    w = exp(-exp(h @ td_w2 + decay)) fp32
    tgemm_k<EPI_TANH, 1><<<dim3(1, 64), tblk, TGP_SMEM>>>(
        Bf + B_WXH, Bf + B_WXL, D_, Bf + B_TD1H, Bf + B_TD1L, D_,
        Bf + B_HH, Bf + B_HL, TD_, D_ / 32, TD_, nullptr);
    tgemm_k<EPI_WDECAY, 0><<<dim3(16, 64), tblk, TGP_SMEM>>>(
        Bf + B_HH, Bf + B_HL, TD_, Bf + B_TD2H, Bf + B_TD2L, TD_,
        S + S_W, nullptr, D_, TD_ / 32, D_, decay);

    // 6) WKV scan
    wkv_kernel<<<B_ * H_, blk>>>(first, st0, out_state);

    // 7) groupnorm + gate → gg (bf16 pair)
    gnorm_kernel<<<BT_ * H_ / 8, blk>>>(ln_g, ln_b);

    // 8) final projection (tensor)
    tgemm_k<EPI_NONE, 0><<<dim3(16, 64), tblk, TGP_SMEM>>>(
        Bf + B_GGH, Bf + B_GGL, D_, Bf + B_WT0 + 8 * WSEG, Bf + B_WT0 + 9 * WSEG, D_,
        out, nullptr, D_, D_ / 32, D_, nullptr);
}